// round 6
// baseline (speedup 1.0000x reference)
#include <cuda_runtime.h>
#include <cuda_fp16.h>
#include <cstdint>

// DistMult edge scorer:
//   out[e] = sigmoid( sum_d z[src,d] * rel[rel_id,d] * z[dst,d] )
// Inputs:
//   d_in[0]: z          float32 [100000, 128]
//   d_in[1]: edge_index int32   [2, E]
//   d_in[2]: rel_id     int32   [E]
//   d_in[3]: rel        float32 [64, 128]
// Output: float32 [E]
//
// Plan:
//  1) convert_kernel: z, rel -> fp16 mirrors (__device__ globals), 16B stores.
//  2) distmult_h: 8 lanes/edge, 4 edges/warp-pass. fp16 rows = 256B = 2 lines;
//     every load instr covers 4 full 128B lines. Math: both multiplies in
//     fp16 (HMUL2 x2), then 2xCVT + one packed add.rn.f32x2 into an fp32-pair
//     accumulator -> 5 instr per 2 dims (was 7). fp32 accumulation.

#define D 128
#define NZ_MAX (100000 * D)
#define NR_MAX (64 * D)
#define FULL 0xFFFFFFFFu

__device__ __half g_zh[NZ_MAX];
__device__ __half g_rh[NR_MAX];

// ---------------- conversion: fp32 -> fp16 mirrors ----------------
__device__ __forceinline__ uint4 cvt8(float4 v0, float4 v1) {
    __half2 h0 = __floats2half2_rn(v0.x, v0.y);
    __half2 h1 = __floats2half2_rn(v0.z, v0.w);
    __half2 h2 = __floats2half2_rn(v1.x, v1.y);
    __half2 h3 = __floats2half2_rn(v1.z, v1.w);
    uint4 o;
    o.x = *reinterpret_cast<unsigned*>(&h0);
    o.y = *reinterpret_cast<unsigned*>(&h1);
    o.z = *reinterpret_cast<unsigned*>(&h2);
    o.w = *reinterpret_cast<unsigned*>(&h3);
    return o;
}

__global__ __launch_bounds__(256) void convert_kernel(
    const float* __restrict__ z, const float* __restrict__ rel,
    int nz, int nr)
{
    int i = blockIdx.x * blockDim.x + threadIdx.x;   // 8 floats per thread
    int nz8 = nz >> 3;
    int nr8 = nr >> 3;
    if (i < nz8) {
        const float4* zp = reinterpret_cast<const float4*>(z);
        reinterpret_cast<uint4*>(g_zh)[i] = cvt8(zp[2 * i], zp[2 * i + 1]);
    } else if (i < nz8 + nr8) {
        int k = i - nz8;
        const float4* rp = reinterpret_cast<const float4*>(rel);
        reinterpret_cast<uint4*>(g_rh)[k] = cvt8(rp[2 * k], rp[2 * k + 1]);
    }
}

// ---------------- main kernel ----------------

// acc2 (packed f32x2) += cvt( (a*c)*b ) for the 2 halves in each word.
__device__ __forceinline__ void dot2p(unsigned a, unsigned c, unsigned b,
                                      unsigned long long& acc2)
{
    __half2 ha = *reinterpret_cast<__half2*>(&a);
    __half2 hc = *reinterpret_cast<__half2*>(&c);
    __half2 hb = *reinterpret_cast<__half2*>(&b);
    __half2 t = __hmul2(ha, hc);
    __half2 u = __hmul2(t, hb);
    float2 uf = __half22float2(u);
    unsigned long long up;
    asm("mov.b64 %0, {%1, %2};" : "=l"(up) : "f"(uf.x), "f"(uf.y));
    asm("add.rn.f32x2 %0, %1, %2;" : "=l"(acc2) : "l"(acc2), "l"(up));
}

__device__ __forceinline__ void dot16p(uint4 a, uint4 c, uint4 b,
                                       unsigned long long& acc2)
{
    dot2p(a.x, c.x, b.x, acc2);
    dot2p(a.y, c.y, b.y, acc2);
    dot2p(a.z, c.z, b.z, acc2);
    dot2p(a.w, c.w, b.w, acc2);
}

__global__ __launch_bounds__(256) void distmult_h(
    const int* __restrict__ edge_index,  // [2, E]
    const int* __restrict__ rel_id,      // [E]
    float* __restrict__ out,
    int E)
{
    int warp_id = (blockIdx.x * blockDim.x + threadIdx.x) >> 5;
    int lane = threadIdx.x & 31;
    int g = lane >> 3;                   // edge group 0..3
    int j = lane & 7;                    // lane within group
    int base = warp_id << 5;             // 32 edges per warp
    if (base >= E) return;

    const uint4* zh = reinterpret_cast<const uint4*>(g_zh);   // 8 uint4 per row... (16B x 8 = 128B? no: 256B row = 16 uint4)
    const uint4* rh = reinterpret_cast<const uint4*>(g_rh);

    #pragma unroll 2
    for (int m = 0; m < 8; ++m) {
        int e = base + (m << 2) + g;
        if (e >= E) break;

        // Group-uniform index loads (4 consecutive values per warp instr).
        int s = edge_index[e];
        int d = edge_index[E + e];
        int r = rel_id[e];

        const uint4* zs = zh + (size_t)s * 16;   // 256B row = 16 uint4
        const uint4* zd = zh + (size_t)d * 16;
        const uint4* rr = rh + (size_t)r * 16;

        // 6 independent 16B loads; each warp instr = 4 full 128B lines.
        uint4 A0 = zs[j], A1 = zs[j + 8];
        uint4 B0 = zd[j], B1 = zd[j + 8];
        uint4 C0 = rr[j], C1 = rr[j + 8];

        unsigned long long acc2 = 0ull;          // packed (0.0f, 0.0f)
        dot16p(A0, C0, B0, acc2);
        dot16p(A1, C1, B1, acc2);

        float lo, hi;
        asm("mov.b64 {%0, %1}, %2;" : "=f"(lo), "=f"(hi) : "l"(acc2));
        float acc = lo + hi;

        // Reduce over 8-lane group; 4 edges share the same 3 shfls.
        acc += __shfl_xor_sync(FULL, acc, 4);
        acc += __shfl_xor_sync(FULL, acc, 2);
        acc += __shfl_xor_sync(FULL, acc, 1);

        if (j == 0) {
            // Lanes 0,8,16,24 -> 4 consecutive floats, one wavefront.
            out[e] = 1.0f / (1.0f + __expf(-acc));
        }
    }
}

extern "C" void kernel_launch(void* const* d_in, const int* in_sizes, int n_in,
                              void* d_out, int out_size)
{
    const float* z          = (const float*)d_in[0];
    const int*   edge_index = (const int*)d_in[1];
    const int*   rel_id     = (const int*)d_in[2];
    const float* rel        = (const float*)d_in[3];
    float*       out        = (float*)d_out;

    int nz = in_sizes[0];            // z element count (<= NZ_MAX)
    int nr = in_sizes[3];            // rel element count
    int E  = in_sizes[2];

    if (nz > NZ_MAX) nz = NZ_MAX;
    if (nr > NR_MAX) nr = NR_MAX;

    // 1) fp32 -> fp16 mirrors (8 floats per thread, 16B stores)
    {
        int work = (nz >> 3) + (nr >> 3);
        int threads = 256;
        int blocks = (work + threads - 1) / threads;
        convert_kernel<<<blocks, threads>>>(z, rel, nz, nr);
    }

    // 2) edge scoring
    {
        const int threads = 256;                 // 8 warps/block, 32 edges/warp
        int edges_per_block = (threads / 32) * 32;
        int blocks = (E + edges_per_block - 1) / edges_per_block;
        distmult_h<<<blocks, threads>>>(edge_index, rel_id, out, E);
    }
}